// round 6
// baseline (speedup 1.0000x reference)
#include <cuda_runtime.h>
#include <cuda_bf16.h>

#define B_    32
#define PRE_  2048
#define POST_ 2048
#define KSPL  32

// ---- static device scratch (no allocations allowed) -------------------------
__device__ float g_part[KSPL * B_ * POST_];   // split-K partials, 8 MB
__device__ float g_tq[B_ * POST_];            // updated post trace
__device__ float g_tp[B_ * PRE_];             // updated pre trace

// =============================================================================
// K1a: split-K forward GEMM partials. grid (POST/128, KSPL), 256 threads.
// Block tile: 32 b x 128 p over a 64-wide K range (2 chunks of 32).
// Thread tile: 4 b x 4 p, float4 smem reads (Wt transposed, xt transposed).
// =============================================================================
__global__ __launch_bounds__(256) void k1a(const float* __restrict__ x,
                                           const float* __restrict__ W) {
    __shared__ float Wt[32][132];   // [k][p_local], stride 132 (16B aligned)
    __shared__ float xt[32][36];    // [k][b],       stride 36  (16B aligned)

    const int tid = threadIdx.x;
    const int p0  = blockIdx.x * 128;
    const int k0  = blockIdx.y * 64;
    const int pg  = tid & 31;        // p_local = pg*4
    const int bg  = tid >> 5;        // b0      = bg*4

    float acc[4][4];
#pragma unroll
    for (int i = 0; i < 4; i++)
#pragma unroll
        for (int j = 0; j < 4; j++) acc[i][j] = 0.0f;

    for (int c = 0; c < 2; ++c) {
        const int kb = k0 + c * 32;
        // stage W[p0..p0+127][kb..kb+31] transposed
        {
            const int r = tid >> 1, seg = tid & 1;
            const float4* wsrc = reinterpret_cast<const float4*>(
                W + (size_t)(p0 + r) * PRE_ + kb + seg * 16);
#pragma unroll
            for (int j = 0; j < 4; ++j) {
                float4 v = wsrc[j];
                int k = seg * 16 + j * 4;
                Wt[k + 0][r] = v.x; Wt[k + 1][r] = v.y;
                Wt[k + 2][r] = v.z; Wt[k + 3][r] = v.w;
            }
        }
        // stage x[0..31][kb..kb+31] transposed
#pragma unroll
        for (int rr = 0; rr < 4; ++rr) {
            int idx = tid + rr * 256;
            int b = idx >> 5, kk = idx & 31;
            xt[kk][b] = x[b * PRE_ + kb + kk];
        }
        __syncthreads();
#pragma unroll
        for (int kk = 0; kk < 32; ++kk) {
            float4 w4 = *reinterpret_cast<const float4*>(&Wt[kk][pg * 4]);
            float4 x4 = *reinterpret_cast<const float4*>(&xt[kk][bg * 4]);
            const float* wv = &w4.x;
            const float* xv = &x4.x;
#pragma unroll
            for (int i = 0; i < 4; ++i)
#pragma unroll
                for (int j = 0; j < 4; ++j)
                    acc[i][j] = fmaf(xv[i], wv[j], acc[i][j]);
        }
        __syncthreads();
    }
    // coalesced float4 epilogue into g_part[split][b][p]
    float* pp = g_part + (size_t)blockIdx.y * (B_ * POST_);
#pragma unroll
    for (int i = 0; i < 4; ++i) {
        float4 o = make_float4(acc[i][0], acc[i][1], acc[i][2], acc[i][3]);
        *reinterpret_cast<float4*>(
            pp + (size_t)(bg * 4 + i) * POST_ + p0 + pg * 4) = o;
    }
}

// =============================================================================
// K1b: reduce split-K partials -> spike; update traces. grid 256 x 256 thr.
// (B*POST == B*PRE == 65536, so one index space covers both trace updates.)
// =============================================================================
__global__ __launch_bounds__(256) void k1b(const float* __restrict__ x,
                                           const float* __restrict__ tpre,
                                           const float* __restrict__ tpost,
                                           float* __restrict__ out_spike) {
    const int idx = blockIdx.x * 256 + threadIdx.x;
    float s = 0.0f;
#pragma unroll
    for (int k = 0; k < KSPL; ++k) s += g_part[(size_t)k * (B_ * POST_) + idx];
    float spike = (s >= 1.0f) ? 1.0f : 0.0f;
    out_spike[idx] = spike;
    g_tq[idx] = 0.5f * tpost[idx] + spike;     // trace_post update (tau=2)
    g_tp[idx] = 0.5f * tpre[idx] + x[idx];     // trace_pre  update (tau=2)
}

// =============================================================================
// K2: dw[p][q] = clip(W[p][q]) * (sum_b spike[b][p]*tp[b][q] - tq[b][p]*x[b][q])
// grid (POST/64, PRE/64), 256 threads. Tile 64p x 64q, thread 4p x 4q.
// =============================================================================
__global__ __launch_bounds__(256) void k2(const float* __restrict__ x,
                                          const float* __restrict__ W,
                                          const float* __restrict__ spike,
                                          float* __restrict__ dw) {
    __shared__ float sp [B_][68];   // spike[b][p_tile]
    __shared__ float tqn[B_][68];   // -tq [b][p_tile]
    __shared__ float tp [B_][68];   // tp  [b][q_tile]
    __shared__ float xs [B_][68];   // x   [b][q_tile]

    const int tid = threadIdx.x;
    const int p0 = blockIdx.x * 64, q0 = blockIdx.y * 64;
    const int qg = tid & 15;         // q_local = qg*4
    const int pg = tid >> 4;         // p_local = pg*4

    // stage 4 tiles of 32x64 (8 elems / thread each, coalesced loads)
#pragma unroll
    for (int r = 0; r < 8; ++r) {
        int idx = tid + r * 256;
        int b = idx >> 6, e = idx & 63;
        sp [b][e] =  spike[b * POST_ + p0 + e];
        tqn[b][e] = -g_tq [b * POST_ + p0 + e];
        tp [b][e] =  g_tp [b * PRE_  + q0 + e];
        xs [b][e] =  x    [b * PRE_  + q0 + e];
    }
    __syncthreads();

    float acc[4][4];
#pragma unroll
    for (int i = 0; i < 4; i++)
#pragma unroll
        for (int j = 0; j < 4; j++) acc[i][j] = 0.0f;

#pragma unroll
    for (int b = 0; b < B_; ++b) {
        float4 s4 = *reinterpret_cast<const float4*>(&sp [b][pg * 4]);
        float4 t4 = *reinterpret_cast<const float4*>(&tqn[b][pg * 4]);
        float4 u4 = *reinterpret_cast<const float4*>(&tp [b][qg * 4]);
        float4 v4 = *reinterpret_cast<const float4*>(&xs [b][qg * 4]);
        const float* sv = &s4.x; const float* tv = &t4.x;
        const float* uv = &u4.x; const float* vv = &v4.x;
#pragma unroll
        for (int i = 0; i < 4; ++i)
#pragma unroll
            for (int j = 0; j < 4; ++j) {
                acc[i][j] = fmaf(sv[i], uv[j], acc[i][j]);
                acc[i][j] = fmaf(tv[i], vv[j], acc[i][j]);
            }
    }

    // epilogue: read W tile, clip, scale, store dw (float4, coalesced)
#pragma unroll
    for (int i = 0; i < 4; ++i) {
        int row = p0 + pg * 4 + i;
        float4 w4 = *reinterpret_cast<const float4*>(
            W + (size_t)row * PRE_ + q0 + qg * 4);
        float4 o;
        o.x = fminf(fmaxf(w4.x, -1.0f), 1.0f) * acc[i][0];
        o.y = fminf(fmaxf(w4.y, -1.0f), 1.0f) * acc[i][1];
        o.z = fminf(fmaxf(w4.z, -1.0f), 1.0f) * acc[i][2];
        o.w = fminf(fmaxf(w4.w, -1.0f), 1.0f) * acc[i][3];
        *reinterpret_cast<float4*>(dw + (size_t)row * PRE_ + q0 + qg * 4) = o;
    }
}

// =============================================================================
extern "C" void kernel_launch(void* const* d_in, const int* in_sizes, int n_in,
                              void* d_out, int out_size) {
    const float* x     = (const float*)d_in[0];   // [32, 2048]
    const float* W     = (const float*)d_in[1];   // [2048, 2048]
    const float* tpre  = (const float*)d_in[2];   // [32, 2048]
    const float* tpost = (const float*)d_in[3];   // [32, 2048]
    float* out      = (float*)d_out;
    float* spike_o  = out;                        // [32, 2048]
    float* dw_o     = out + B_ * POST_;           // [2048, 2048]

    k1a<<<dim3(POST_ / 128, KSPL), 256>>>(x, W);
    k1b<<<(B_ * POST_) / 256, 256>>>(x, tpre, tpost, spike_o);
    k2<<<dim3(POST_ / 64, PRE_ / 64), 256>>>(x, W, spike_o, dw_o);
}